// round 14
// baseline (speedup 1.0000x reference)
#include <cuda_runtime.h>
#include <cuda_fp16.h>
#include <math.h>

#define NB     4096
#define NG     16
#define NIN    1024
#define NHID   2048
#define NPROJ  256
#define NCHUNK 4096
#define OUTLD  (NG*NCHUNK)   /* 65536 */

// Scratch (device globals — no allocation allowed)
__device__ __half g_z16[(size_t)NB*NIN];            // 8 MB
__device__ __half g_w1t16[(size_t)NG*NHID*NIN];     // 64 MB  W1^T [g][n][k]
__device__ __half g_w2t16[(size_t)NG*NPROJ*NHID];   // 16 MB  W2^T [g][p][h]
__device__ __half g_h16[(size_t)NG*NB*NHID];        // 256 MB h then LN+GELU(h)
__device__ __half g_qn16[(size_t)NG*NB*NPROJ];      // 32 MB  q then normalized q
__device__ __half g_wv16[(size_t)NG*NCHUNK*NPROJ];  // 32 MB  fp16 copy of Wv
__device__ float  g_ss[(size_t)NG*NB*2];            // partial sumsq per row-half
__device__ float  g_coef[NG*NCHUNK];

__device__ __forceinline__ unsigned s2u(const void* p){
  return (unsigned)__cvta_generic_to_shared(p);
}
__device__ __forceinline__ void cpa16(void* s, const void* g){
  asm volatile("cp.async.cg.shared.global [%0], [%1], 16;\n"
    :: "r"(s2u(s)), "l"(g));
}
__device__ __forceinline__ void ldsm4(unsigned &r0, unsigned &r1, unsigned &r2, unsigned &r3, unsigned addr){
  asm volatile("ldmatrix.sync.aligned.m8n8.x4.shared.b16 {%0,%1,%2,%3}, [%4];\n"
    : "=r"(r0), "=r"(r1), "=r"(r2), "=r"(r3) : "r"(addr) : "memory");
}
__device__ __forceinline__ void mma16(float* c, const unsigned* a, unsigned b0, unsigned b1){
  asm volatile(
    "mma.sync.aligned.m16n8k16.row.col.f32.f16.f16.f32 "
    "{%0,%1,%2,%3}, {%4,%5,%6,%7}, {%8,%9}, {%0,%1,%2,%3};\n"
    : "+f"(c[0]), "+f"(c[1]), "+f"(c[2]), "+f"(c[3])
    : "r"(a[0]), "r"(a[1]), "r"(a[2]), "r"(a[3]), "r"(b0), "r"(b1));
}

// ===========================================================================
// fp16 mainloop: block 128x128, BK=64 halves, 3-stage ring, 256 threads,
// 2 CTAs/SM. Warp grid 2(m) x 4(n); warp tile 64x32 (mt=4, 2 ldmatrix.x4 B).
// ===========================================================================
#define H_STRIDE 72                 /* halves: 64+8 pad; 72*2=144B ≡ 16 mod 128 */
#define H_TSZ (128*H_STRIDE)        /* halves per tile */
#define SMEM_H (3*2*H_TSZ*2)        /* 110,592 B */

__device__ __forceinline__ void mma_loop_h(
  const __half* __restrict__ Ap, const __half* __restrict__ Bp,
  int lda, int ldb, int KT, __half* sm, float (&c)[4][4][4])
{
  const int tid  = threadIdx.x;
  const int lane = tid & 31, wid = tid >> 5;
  const int wm   = (wid & 1) * 64;
  const int wn   = (wid >> 1) * 32;
  const int srow = tid >> 3, scol = (tid & 7) << 3;   // halves

  #pragma unroll
  for (int i=0;i<4;i++)
    #pragma unroll
    for (int j=0;j<4;j++)
      #pragma unroll
      for (int k=0;k<4;k++) c[i][j][k]=0.f;

  auto issue = [&](int s, int k0){
    __half* as = sm + s*2*H_TSZ;
    __half* bs = as + H_TSZ;
    #pragma unroll
    for (int i=0;i<4;i++)
      cpa16(&as[(srow+32*i)*H_STRIDE + scol], Ap + (size_t)(srow+32*i)*lda + k0 + scol);
    #pragma unroll
    for (int i=0;i<4;i++)
      cpa16(&bs[(srow+32*i)*H_STRIDE + scol], Bp + (size_t)(srow+32*i)*ldb + k0 + scol);
    asm volatile("cp.async.commit_group;\n" ::: "memory");
  };
  issue(0, 0);
  issue(1, 64);

  // fragment address lanes (b16 elements)
  const int a_r  = lane & 15;              // m row within 16
  const int a_ch = (lane >> 4) * 8;        // k halves 0 / 8
  const int b_r  = (lane & 7) + ((lane >> 3) & 1) * 8;  // n row within 16
  const int b_ch = (lane >> 4) * 8;        // k halves 0 / 8

  for (int kt = 0; kt < KT; kt++){
    asm volatile("cp.async.wait_group 1;\n" ::: "memory");
    __syncthreads();
    if (kt+2 < KT) issue((kt+2)%3, (kt+2)*64);
    else asm volatile("cp.async.commit_group;\n" ::: "memory");

    const unsigned as0 = s2u(sm + (kt%3)*2*H_TSZ);
    const unsigned bs0 = as0 + (unsigned)(H_TSZ*2);
    #pragma unroll
    for (int ks=0; ks<4; ks++){
      const int kb = ks*16;
      unsigned a[4][4], b[2][4];
      #pragma unroll
      for (int mt=0;mt<4;mt++){
        unsigned ad = as0 + (unsigned)(((wm + mt*16 + a_r)*H_STRIDE + kb + a_ch)*2);
        ldsm4(a[mt][0],a[mt][1],a[mt][2],a[mt][3], ad);
      }
      #pragma unroll
      for (int np=0;np<2;np++){
        unsigned bd = bs0 + (unsigned)(((wn + np*16 + b_r)*H_STRIDE + kb + b_ch)*2);
        ldsm4(b[np][0],b[np][1],b[np][2],b[np][3], bd);
      }
      #pragma unroll
      for (int mt=0;mt<4;mt++)
        #pragma unroll
        for (int np=0;np<2;np++){
          mma16(c[mt][np*2+0], a[mt], b[np][0], b[np][2]);
          mma16(c[mt][np*2+1], a[mt], b[np][1], b[np][3]);
        }
    }
  }
  __syncthreads();
}

// ---------------------------------------------------------------------------
// k_cvt: fp32 -> fp16, 8 elements/thread
// ---------------------------------------------------------------------------
__global__ void k_cvt(const float* __restrict__ src, __half* __restrict__ dst)
{
  const int i = blockIdx.x*256 + threadIdx.x;
  float4 a = ((const float4*)src)[i*2];
  float4 b = ((const float4*)src)[i*2+1];
  union { __half2 h[4]; uint4 u; } p;
  p.h[0] = __floats2half2_rn(a.x, a.y);
  p.h[1] = __floats2half2_rn(a.z, a.w);
  p.h[2] = __floats2half2_rn(b.x, b.y);
  p.h[3] = __floats2half2_rn(b.z, b.w);
  ((uint4*)dst)[i] = p.u;
}

// ---------------------------------------------------------------------------
// Transpose + convert: src fp32 [g][R][C] -> dst fp16 [g][C][R]
// ---------------------------------------------------------------------------
__global__ void k_tr_h(const float* __restrict__ src, __half* __restrict__ dst, int R, int C)
{
  __shared__ float t[32][33];
  const int g = blockIdx.z;
  src += (size_t)g*R*C;
  dst += (size_t)g*R*C;
  const int c0 = blockIdx.x*32, r0 = blockIdx.y*32;
  const int x = threadIdx.x, y = threadIdx.y;
  #pragma unroll
  for (int j=0;j<32;j+=8)
    t[y+j][x] = src[(size_t)(r0+y+j)*C + c0+x];
  __syncthreads();
  #pragma unroll
  for (int j=0;j<32;j+=8)
    dst[(size_t)(c0+y+j)*R + r0+x] = __float2half(t[x][y+j]);
}

// ---------------------------------------------------------------------------
// GEMM1: h = z @ W1 + b1 -> g_h16 (fp16)
// ---------------------------------------------------------------------------
__global__ void __launch_bounds__(256,2) k_gemm1(const float* __restrict__ b1)
{
  extern __shared__ __half sm[];
  const int g  = blockIdx.z;
  const int m0 = blockIdx.y * 128;
  const int n0 = blockIdx.x * 128;
  const __half* Ap = g_z16 + (size_t)m0 * NIN;
  const __half* Bp = g_w1t16 + (size_t)g*NHID*NIN + (size_t)n0*NIN;

  float c[4][4][4];
  mma_loop_h(Ap, Bp, NIN, NIN, NIN/64, sm, c);

  const int lane = threadIdx.x & 31, wid = threadIdx.x >> 5;
  const int wm = (wid & 1)*64, wn = (wid >> 1)*32;
  const int gid = lane >> 2, tig = lane & 3;
  const float* b1g = b1 + g*NHID + n0;
  __half* H = g_h16 + ((size_t)g*NB + m0) * NHID + n0;
  #pragma unroll
  for (int mt=0;mt<4;mt++)
    #pragma unroll
    for (int half=0; half<2; half++){
      const int r = wm + mt*16 + half*8 + gid;
      #pragma unroll
      for (int nt=0;nt<4;nt++){
        const int n = wn + nt*8 + tig*2;
        *(__half2*)(H + (size_t)r*NHID + n) =
          __floats2half2_rn(c[mt][nt][half*2+0] + b1g[n],
                            c[mt][nt][half*2+1] + b1g[n+1]);
      }
    }
}

// ---------------------------------------------------------------------------
// K2: per-row LayerNorm + exact-erf GELU, in place on g_h16. 1 block / row.
// ---------------------------------------------------------------------------
__global__ void __launch_bounds__(256) k_lngelu(
    const float* __restrict__ ln_g, const float* __restrict__ ln_b)
{
  const int row = blockIdx.x;           // 0 .. G*B-1
  const int g   = row >> 12;
  __half* base = g_h16 + (size_t)row * NHID;
  const int tid = threadIdx.x;
  const int lane = tid & 31, wid = tid >> 5;

  union { __half2 h[4]; uint4 u; } p;
  p.u = ((const uint4*)base)[tid];
  float xs[8];
  #pragma unroll
  for (int j=0;j<4;j++){
    float2 f = __half22float2(p.h[j]);
    xs[2*j] = f.x; xs[2*j+1] = f.y;
  }
  float s = 0.f, q = 0.f;
  #pragma unroll
  for (int j=0;j<8;j++){ s += xs[j]; q += xs[j]*xs[j]; }
  #pragma unroll
  for (int o=16;o;o>>=1){
    s += __shfl_xor_sync(0xffffffffu, s, o);
    q += __shfl_xor_sync(0xffffffffu, q, o);
  }
  __shared__ float rs[8], rq[8];
  if (lane==0){ rs[wid]=s; rq[wid]=q; }
  __syncthreads();
  if (tid==0){
    float S=0.f, Q=0.f;
    #pragma unroll
    for (int i=0;i<8;i++){ S+=rs[i]; Q+=rq[i]; }
    rs[0]=S; rq[0]=Q;
  }
  __syncthreads();
  const float S = rs[0], Q = rq[0];
  const float mu   = S * (1.f/NHID);
  const float var  = Q * (1.f/NHID) - mu*mu;
  const float rsig = rsqrtf(var + 1e-5f);

  const float* lg = ln_g + g*NHID + tid*8;
  const float* lb = ln_b + g*NHID + tid*8;
  const float isq2 = 0.70710678118654752440f;
  float ys[8];
  #pragma unroll
  for (int j=0;j<8;j++){
    float y = (xs[j]-mu)*rsig*lg[j] + lb[j];
    ys[j] = 0.5f*y*(1.f + erff(y*isq2));
  }
  #pragma unroll
  for (int j=0;j<4;j++)
    p.h[j] = __floats2half2_rn(ys[2*j], ys[2*j+1]);
  ((uint4*)base)[tid] = p.u;
}

// ---------------------------------------------------------------------------
// K3: coef[g,v] = min(exp(ls[g]),100)/max(||Wv[g,v]||,1e-12); also Wv->fp16.
// ---------------------------------------------------------------------------
__global__ void __launch_bounds__(256) k_coef(
    const float* __restrict__ Wv, const float* __restrict__ logit_scale)
{
  const int tid = threadIdx.x;
  const int wid = tid >> 5, lane = tid & 31;
  const int row = blockIdx.x * 8 + wid;     // 0 .. G*CHUNK-1
  const float* p = Wv + (size_t)row * NPROJ;
  float4 a = ((const float4*)p)[lane];
  float4 b = ((const float4*)p)[lane + 32];

  __half2* w16 = (__half2*)(g_wv16 + (size_t)row * NPROJ);
  w16[lane*2+0]    = __floats2half2_rn(a.x, a.y);
  w16[lane*2+1]    = __floats2half2_rn(a.z, a.w);
  w16[64+lane*2+0] = __floats2half2_rn(b.x, b.y);
  w16[64+lane*2+1] = __floats2half2_rn(b.z, b.w);

  float s = a.x*a.x+a.y*a.y+a.z*a.z+a.w*a.w
          + b.x*b.x+b.y*b.y+b.z*b.z+b.w*b.w;
  #pragma unroll
  for (int o=16;o;o>>=1) s += __shfl_xor_sync(0xffffffffu, s, o);
  if (lane==0){
    const int g = row >> 12;
    const float sc = fminf(expf(logit_scale[g]), 100.f);
    g_coef[row] = sc / fmaxf(sqrtf(s), 1e-12f);
  }
}

// ---------------------------------------------------------------------------
// GEMM2: q = gelu_h @ W2 + b2 -> g_qn16 (unnormalized fp16) + g_ss partials.
// ---------------------------------------------------------------------------
__global__ void __launch_bounds__(256,2) k_gemm2(const float* __restrict__ b2)
{
  extern __shared__ __half sm[];
  const int g  = blockIdx.z;
  const int m0 = blockIdx.y * 128;
  const int hx = blockIdx.x;              // 0 or 1 (n-half)
  const int n0 = hx * 128;
  const __half* Ap = g_h16 + ((size_t)g*NB + m0) * NHID;
  const __half* Bp = g_w2t16 + (size_t)g*NPROJ*NHID + (size_t)n0*NHID;

  float c[4][4][4];
  mma_loop_h(Ap, Bp, NHID, NHID, NHID/64, sm, c);

  const int tid = threadIdx.x;
  const int lane = tid & 31, wid = tid >> 5;
  const int wm = (wid & 1)*64, wn = (wid >> 1)*32;
  const int gid = lane >> 2, tig = lane & 3;

  float* rp = (float*)sm;   // [128][4] partials (smem free after mainloop)

  const float* b2g = b2 + g*NPROJ + n0;
  #pragma unroll
  for (int mt=0;mt<4;mt++)
    #pragma unroll
    for (int half=0; half<2; half++){
      const int r = wm + mt*16 + half*8 + gid;
      float ps = 0.f;
      #pragma unroll
      for (int nt=0;nt<4;nt++){
        const int n = wn + nt*8 + tig*2;
        float x = c[mt][nt][half*2+0] + b2g[n];
        float y = c[mt][nt][half*2+1] + b2g[n+1];
        c[mt][nt][half*2+0] = x;
        c[mt][nt][half*2+1] = y;
        ps += x*x + y*y;
      }
      ps += __shfl_xor_sync(0xffffffffu, ps, 1);
      ps += __shfl_xor_sync(0xffffffffu, ps, 2);
      if (tig==0) rp[r*4 + (wid>>1)] = ps;
    }
  __syncthreads();
  if (tid < 128){
    const float ss = rp[tid*4+0]+rp[tid*4+1]+rp[tid*4+2]+rp[tid*4+3];
    g_ss[((size_t)g*NB + m0 + tid)*2 + hx] = ss;
  }
  __half* Qp = g_qn16 + ((size_t)g*NB + m0) * NPROJ + n0;
  #pragma unroll
  for (int mt=0;mt<4;mt++)
    #pragma unroll
    for (int half=0; half<2; half++){
      const int r = wm + mt*16 + half*8 + gid;
      #pragma unroll
      for (int nt=0;nt<4;nt++){
        const int n = wn + nt*8 + tig*2;
        *(__half2*)(Qp + (size_t)r*NPROJ + n) =
          __floats2half2_rn(c[mt][nt][half*2+0], c[mt][nt][half*2+1]);
      }
    }
}

// ---------------------------------------------------------------------------
// k_qnorm: g_qn16 row-normalize in place using g_ss partials. 8 rows/block.
// ---------------------------------------------------------------------------
__global__ void __launch_bounds__(256) k_qnorm()
{
  const int row = blockIdx.x * 8 + (threadIdx.x >> 5);
  const int lane = threadIdx.x & 31;
  const float ss = g_ss[row*2+0] + g_ss[row*2+1];
  const float inv = 1.f / fmaxf(sqrtf(ss), 1e-12f);
  uint4* p = (uint4*)(g_qn16 + (size_t)row * NPROJ);
  union { __half2 h[4]; uint4 u; } v;
  v.u = p[lane];
  #pragma unroll
  for (int j=0;j<4;j++){
    float2 f = __half22float2(v.h[j]);
    v.h[j] = __floats2half2_rn(f.x*inv, f.y*inv);
  }
  p[lane] = v.u;
}

// ---------------------------------------------------------------------------
// GEMM3: out[b, g*CHUNK+v] = (qn . Wv[g,v]) * coef[g,v] + bv[g,v]
// ---------------------------------------------------------------------------
__global__ void __launch_bounds__(256,2) k_gemm3(
    const float* __restrict__ bv, float* __restrict__ out)
{
  extern __shared__ __half sm[];
  const int g  = blockIdx.z;
  const int m0 = blockIdx.y * 128;
  const int n0 = blockIdx.x * 128;
  const __half* Ap = g_qn16 + ((size_t)g*NB + m0) * NPROJ;
  const __half* Bp = g_wv16 + ((size_t)g*NCHUNK + n0) * NPROJ;

  float c[4][4][4];
  mma_loop_h(Ap, Bp, NPROJ, NPROJ, NPROJ/64, sm, c);

  const int lane = threadIdx.x & 31, wid = threadIdx.x >> 5;
  const int wm = (wid & 1)*64, wn = (wid >> 1)*32;
  const int gid = lane >> 2, tig = lane & 3;

  const float* cf  = g_coef + g*NCHUNK + n0;
  const float* bvg = bv     + g*NCHUNK + n0;
  float* O = out + (size_t)m0 * OUTLD + (size_t)g*NCHUNK + n0;
  #pragma unroll
  for (int mt=0;mt<4;mt++)
    #pragma unroll
    for (int half=0; half<2; half++){
      const int r = wm + mt*16 + half*8 + gid;
      #pragma unroll
      for (int nt=0;nt<4;nt++){
        const int n = wn + nt*8 + tig*2;
        float2 v;
        v.x = c[mt][nt][half*2+0]*cf[n]   + bvg[n];
        v.y = c[mt][nt][half*2+1]*cf[n+1] + bvg[n+1];
        *(float2*)(O + (size_t)r*OUTLD + n) = v;
      }
    }
}

// ---------------------------------------------------------------------------
extern "C" void kernel_launch(void* const* d_in, const int* in_sizes, int n_in,
                              void* d_out, int out_size)
{
  (void)in_sizes; (void)n_in; (void)out_size;
  const float* z   = (const float*)d_in[0];
  const float* W1  = (const float*)d_in[1];
  const float* b1  = (const float*)d_in[2];
  const float* lng = (const float*)d_in[3];
  const float* lnb = (const float*)d_in[4];
  const float* W2  = (const float*)d_in[5];
  const float* b2  = (const float*)d_in[6];
  const float* Wv  = (const float*)d_in[7];
  const float* bv  = (const float*)d_in[8];
  const float* ls  = (const float*)d_in[9];
  float* out = (float*)d_out;

  cudaFuncSetAttribute(k_gemm1, cudaFuncAttributeMaxDynamicSharedMemorySize, SMEM_H);
  cudaFuncSetAttribute(k_gemm2, cudaFuncAttributeMaxDynamicSharedMemorySize, SMEM_H);
  cudaFuncSetAttribute(k_gemm3, cudaFuncAttributeMaxDynamicSharedMemorySize, SMEM_H);

  __half* z16;  cudaGetSymbolAddress((void**)&z16,  g_z16);
  __half* w1t;  cudaGetSymbolAddress((void**)&w1t,  g_w1t16);
  __half* w2t;  cudaGetSymbolAddress((void**)&w2t,  g_w2t16);

  // Prologue: conversions / transposes / coef
  k_cvt <<<NB*NIN/(256*8), 256>>>(z, z16);
  k_tr_h<<<dim3(NHID/32, NIN/32,  NG), dim3(32,8)>>>(W1, w1t, NIN,  NHID);
  k_tr_h<<<dim3(NPROJ/32, NHID/32, NG), dim3(32,8)>>>(W2, w2t, NHID, NPROJ);
  k_coef<<<NG*NCHUNK/8, 256>>>(Wv, ls);

  k_gemm1 <<<dim3(NHID/128, NB/128, NG), 256, SMEM_H>>>(b1);
  k_lngelu<<<NG*NB, 256>>>(lng, lnb);
  k_gemm2 <<<dim3(2, NB/128, NG), 256, SMEM_H>>>(b2);
  k_qnorm <<<NG*NB/8, 256>>>();
  k_gemm3 <<<dim3(NCHUNK/128, NB/128, NG), 256, SMEM_H>>>(bv, out);
}

// round 16
// speedup vs baseline: 1.1119x; 1.1119x over previous
#include <cuda_runtime.h>
#include <cuda_bf16.h>
#include <math.h>

#define NB     4096
#define NG     16
#define NIN    1024
#define NHID   2048
#define NPROJ  256
#define NCHUNK 4096
#define OUTLD  (NG*NCHUNK)   /* 65536 */

// Scratch (device globals — no allocation allowed)
__device__ float g_h[(size_t)NG*NB*NHID];        // 512 MB
__device__ float g_qn[(size_t)NG*NB*NPROJ];      // 16 MB
__device__ float g_ss[(size_t)NG*NB*2];          // partial sumsq per row-half
__device__ float g_coef[NG*NCHUNK];
__device__ float g_w1t[(size_t)NG*NHID*NIN];     // 128 MB  W1^T [g][n][k]
__device__ float g_w2t[(size_t)NG*NPROJ*NHID];   // 8 MB    W2^T [g][p][h]

__device__ __forceinline__ unsigned s2u(const void* p){
  return (unsigned)__cvta_generic_to_shared(p);
}
__device__ __forceinline__ void cpa16(void* s, const void* g){
  asm volatile("cp.async.cg.shared.global [%0], [%1], 16;\n"
    :: "r"(s2u(s)), "l"(g));
}
__device__ __forceinline__ void ldsm4(unsigned &r0, unsigned &r1, unsigned &r2, unsigned &r3, unsigned addr){
  asm volatile("ldmatrix.sync.aligned.m8n8.x4.shared.b16 {%0,%1,%2,%3}, [%4];\n"
    : "=r"(r0), "=r"(r1), "=r"(r2), "=r"(r3) : "r"(addr) : "memory");
}
__device__ __forceinline__ void mma8(float* c, const unsigned* a, const unsigned* b){
  asm volatile(
    "mma.sync.aligned.m16n8k8.row.col.f32.tf32.tf32.f32 "
    "{%0,%1,%2,%3}, {%4,%5,%6,%7}, {%8,%9}, {%0,%1,%2,%3};\n"
    : "+f"(c[0]), "+f"(c[1]), "+f"(c[2]), "+f"(c[3])
    : "r"(a[0]), "r"(a[1]), "r"(a[2]), "r"(a[3]), "r"(b[0]), "r"(b[1]));
}

// mbarrier helpers
#define MBAR_INIT(a, c) \
  asm volatile("mbarrier.init.shared.b64 [%0], %1;" :: "r"((unsigned)(a)), "r"((unsigned)(c)) : "memory")
#define MBAR_ARRIVE(a) \
  asm volatile("mbarrier.arrive.shared.b64 _, [%0];" :: "r"((unsigned)(a)) : "memory")
// .noinc: deferred arrive counts against the init count (default variant
// would increment expected-count first and deadlock a pure-async barrier).
#define CPA_MBAR_ARRIVE(a) \
  asm volatile("cp.async.mbarrier.arrive.noinc.shared.b64 [%0];" :: "r"((unsigned)(a)) : "memory")
#define MBAR_WAIT(mbar_a, par) do { \
  unsigned _m = (unsigned)(mbar_a); unsigned _p = (unsigned)(par); unsigned _d; \
  asm volatile("{\n\t.reg .pred p;\n\t" \
    "mbarrier.try_wait.parity.acquire.cta.shared::cta.b64 p, [%1], %2;\n\t" \
    "selp.b32 %0, 1, 0, p;\n\t}" : "=r"(_d) : "r"(_m), "r"(_p) : "memory"); \
  if (!_d) { \
    asm volatile("{\n\t.reg .pred P1;\n\t" \
      "WL_%=:\n\t" \
      "mbarrier.try_wait.parity.acquire.cta.shared::cta.b64 P1, [%0], %1, 0x989680;\n\t" \
      "@P1 bra.uni WD_%=;\n\t" \
      "bra.uni WL_%=;\n\t" \
      "WD_%=:\n\t}" :: "r"(_m), "r"(_p) : "memory"); \
  } \
} while(0)

// ===========================================================================
// Variant A (all GEMMs): block 128x128, BK=32, 3-stage ring, 256 threads,
// 2 CTAs/SM. Warp grid 2(m) x 4(n); warp tile 64x32 (mt=4 x nt=4).
// Stage sync via mbarrier pipeline (full/empty per stage) — warps may skew.
// ===========================================================================
#define A_STRIDE 36                /* 32+4 pad; 36*4=144 ≡ 16 (mod 128) */
#define A_TSZ (128*A_STRIDE)       /* one 128-row tile, floats */
#define MBAR_OFF (6*A_TSZ*4)       /* byte offset of barriers in dynamic smem */
#define SMEM_A (MBAR_OFF + 64)     /* 110,656 B */

__device__ __forceinline__ void mma_loop_128(
  const float* __restrict__ Ap, const float* __restrict__ Bp,
  int lda, int ldb, int KT, float* sm, float (&c)[4][4][4])
{
  const int tid  = threadIdx.x;
  const int lane = tid & 31, wid = tid >> 5;
  const int wm   = (wid & 1) * 64;
  const int wn   = (wid >> 1) * 32;
  const int srow = tid >> 3, scol = (tid & 7) << 2;

  const unsigned mb   = s2u(sm) + MBAR_OFF;      // full[0..2] at +0,+8,+16
  const unsigned mbE  = mb + 24;                 // empty[0..2] at +24,+32,+40

  if (tid == 0){
    #pragma unroll
    for (int i=0;i<3;i++){ MBAR_INIT(mb + i*8, 256); MBAR_INIT(mbE + i*8, 256); }
  }
  __syncthreads();

  #pragma unroll
  for (int i=0;i<4;i++)
    #pragma unroll
    for (int j=0;j<4;j++)
      #pragma unroll
      for (int k=0;k<4;k++) c[i][j][k]=0.f;

  auto issue = [&](int s, int k0){
    float* as = sm + s*2*A_TSZ;
    float* bs = as + A_TSZ;
    #pragma unroll
    for (int i=0;i<4;i++)
      cpa16(&as[(srow+32*i)*A_STRIDE + scol], Ap + (size_t)(srow+32*i)*lda + k0 + scol);
    #pragma unroll
    for (int i=0;i<4;i++)
      cpa16(&bs[(srow+32*i)*A_STRIDE + scol], Bp + (size_t)(srow+32*i)*ldb + k0 + scol);
    CPA_MBAR_ARRIVE(mb + s*8);
  };
  issue(0, 0);
  issue(1, 32);

  const int a_r  = lane & 15;
  const int a_c4 = (lane >> 4) * 4;
  const int b_r  = (lane & 7) + ((lane >> 4) & 1) * 8;
  const int b_c4 = ((lane >> 3) & 1) * 4;

  for (int kt = 0; kt < KT; kt++){
    const int s  = kt % 3;
    const int ph = (kt / 3) & 1;

    // producer for stage kt+2
    const int kl = kt + 2;
    if (kl < KT){
      const int sl = kl % 3;
      if (kl >= 3) MBAR_WAIT(mbE + sl*8, ((kl - 3) / 3) & 1);
      issue(sl, kl*32);
    }

    // consumer: wait data for stage kt (per-thread, no CTA alignment)
    MBAR_WAIT(mb + s*8, ph);

    const unsigned as0 = s2u(sm + s*2*A_TSZ);
    const unsigned bs0 = as0 + (unsigned)(A_TSZ*4);
    #pragma unroll
    for (int ks=0; ks<4; ks++){
      const int kb = ks*8;
      unsigned a[4][4], b[2][4];
      #pragma unroll
      for (int mt=0;mt<4;mt++){
        unsigned ad = as0 + (unsigned)(((wm + mt*16 + a_r)*A_STRIDE + kb + a_c4)*4);
        ldsm4(a[mt][0],a[mt][1],a[mt][2],a[mt][3], ad);
      }
      #pragma unroll
      for (int np=0;np<2;np++){
        unsigned bd = bs0 + (unsigned)(((wn + np*16 + b_r)*A_STRIDE + kb + b_c4)*4);
        ldsm4(b[np][0],b[np][1],b[np][2],b[np][3], bd);
      }
      #pragma unroll
      for (int mt=0;mt<4;mt++)
        #pragma unroll
        for (int np=0;np<2;np++){
          mma8(c[mt][np*2+0], a[mt], &b[np][0]);
          mma8(c[mt][np*2+1], a[mt], &b[np][2]);
        }
    }
    MBAR_ARRIVE(mbE + s*8);
  }
  __syncthreads();
}

// ---------------------------------------------------------------------------
// Transpose: src [g][R][C] -> dst [g][C][R]
// ---------------------------------------------------------------------------
__global__ void k_tr(const float* __restrict__ src, float* __restrict__ dst, int R, int C)
{
  __shared__ float t[32][33];
  const int g = blockIdx.z;
  src += (size_t)g*R*C;
  dst += (size_t)g*R*C;
  const int c0 = blockIdx.x*32, r0 = blockIdx.y*32;
  const int x = threadIdx.x, y = threadIdx.y;
  #pragma unroll
  for (int j=0;j<32;j+=8)
    t[y+j][x] = src[(size_t)(r0+y+j)*C + c0+x];
  __syncthreads();
  #pragma unroll
  for (int j=0;j<32;j+=8)
    dst[(size_t)(c0+y+j)*R + r0+x] = t[x][y+j];
}

// ---------------------------------------------------------------------------
// GEMM1: h = z @ W1 + b1   (A=z [4096][1024], B=w1t [g][2048][1024])
// ---------------------------------------------------------------------------
__global__ void __launch_bounds__(256,2) k_gemm1(
    const float* __restrict__ z, const float* __restrict__ b1)
{
  extern __shared__ float sm[];
  const int g  = blockIdx.z;
  const int m0 = blockIdx.y * 128;
  const int n0 = blockIdx.x * 128;
  const float* Ap = z + (size_t)m0 * NIN;
  const float* Bp = g_w1t + (size_t)g*NHID*NIN + (size_t)n0*NIN;

  float c[4][4][4];
  mma_loop_128(Ap, Bp, NIN, NIN, NIN/32, sm, c);

  const int lane = threadIdx.x & 31, wid = threadIdx.x >> 5;
  const int wm = (wid & 1)*64, wn = (wid >> 1)*32;
  const int gid = lane >> 2, tig = lane & 3;
  const float* b1g = b1 + g*NHID + n0;
  float* H = g_h + ((size_t)g*NB + m0) * NHID + n0;
  #pragma unroll
  for (int mt=0;mt<4;mt++)
    #pragma unroll
    for (int half=0; half<2; half++){
      const int r = wm + mt*16 + half*8 + gid;
      #pragma unroll
      for (int nt=0;nt<4;nt++){
        const int n = wn + nt*8 + tig*2;
        float2 v;
        v.x = c[mt][nt][half*2+0] + b1g[n];
        v.y = c[mt][nt][half*2+1] + b1g[n+1];
        *(float2*)(H + (size_t)r*NHID + n) = v;
      }
    }
}

// ---------------------------------------------------------------------------
// K2: per-row LayerNorm + exact-erf GELU, in place on g_h. 1 block / row.
// ---------------------------------------------------------------------------
__global__ void __launch_bounds__(256) k_lngelu(
    const float* __restrict__ ln_g, const float* __restrict__ ln_b)
{
  const int row = blockIdx.x;           // 0 .. G*B-1
  const int g   = row >> 12;
  float* base = g_h + (size_t)row * NHID;
  const int tid = threadIdx.x;
  const int lane = tid & 31, wid = tid >> 5;

  float4 v0 = ((const float4*)base)[tid];
  float4 v1 = ((const float4*)base)[tid + 256];
  float s = v0.x+v0.y+v0.z+v0.w + v1.x+v1.y+v1.z+v1.w;
  float q = v0.x*v0.x+v0.y*v0.y+v0.z*v0.z+v0.w*v0.w
          + v1.x*v1.x+v1.y*v1.y+v1.z*v1.z+v1.w*v1.w;
  #pragma unroll
  for (int o=16;o;o>>=1){
    s += __shfl_xor_sync(0xffffffffu, s, o);
    q += __shfl_xor_sync(0xffffffffu, q, o);
  }
  __shared__ float rs[8], rq[8];
  if (lane==0){ rs[wid]=s; rq[wid]=q; }
  __syncthreads();
  if (tid==0){
    float S=0.f, Q=0.f;
    #pragma unroll
    for (int i=0;i<8;i++){ S+=rs[i]; Q+=rq[i]; }
    rs[0]=S; rq[0]=Q;
  }
  __syncthreads();
  const float S = rs[0], Q = rq[0];
  const float mu   = S * (1.f/NHID);
  const float var  = Q * (1.f/NHID) - mu*mu;
  const float rsig = rsqrtf(var + 1e-5f);

  const float* lg = ln_g + g*NHID;
  const float* lb = ln_b + g*NHID;
  const float isq2 = 0.70710678118654752440f;

  const int c0 = tid*4, c1 = (tid+256)*4;
  float xs[8] = {v0.x,v0.y,v0.z,v0.w, v1.x,v1.y,v1.z,v1.w};
  int   cs[8] = {c0,c0+1,c0+2,c0+3, c1,c1+1,c1+2,c1+3};
  float ys[8];
  #pragma unroll
  for (int i=0;i<8;i++){
    float y = (xs[i]-mu)*rsig*lg[cs[i]] + lb[cs[i]];
    ys[i] = 0.5f*y*(1.f + erff(y*isq2));
  }
  ((float4*)base)[tid]       = make_float4(ys[0],ys[1],ys[2],ys[3]);
  ((float4*)base)[tid + 256] = make_float4(ys[4],ys[5],ys[6],ys[7]);
}

// ---------------------------------------------------------------------------
// K3: coef[g,v] = min(exp(logit_scale[g]),100) / max(||Wv[g,v,:]||, 1e-12)
// ---------------------------------------------------------------------------
__global__ void __launch_bounds__(256) k_coef(
    const float* __restrict__ Wv, const float* __restrict__ logit_scale)
{
  const int tid = threadIdx.x;
  const int wid = tid >> 5, lane = tid & 31;
  const int row = blockIdx.x * 8 + wid;     // 0 .. G*CHUNK-1
  const float* p = Wv + (size_t)row * NPROJ;
  float4 a = ((const float4*)p)[lane];
  float4 b = ((const float4*)p)[lane + 32];
  float s = a.x*a.x+a.y*a.y+a.z*a.z+a.w*a.w
          + b.x*b.x+b.y*b.y+b.z*b.z+b.w*b.w;
  #pragma unroll
  for (int o=16;o;o>>=1) s += __shfl_xor_sync(0xffffffffu, s, o);
  if (lane==0){
    const int g = row >> 12;
    const float sc = fminf(expf(logit_scale[g]), 100.f);
    g_coef[row] = sc / fmaxf(sqrtf(s), 1e-12f);
  }
}

// ---------------------------------------------------------------------------
// GEMM2: q = gelu_h @ W2 + b2 -> g_qn (unnormalized) + per-half sumsq g_ss.
// 128x128 tiles, 2 CTAs per m-row (blockIdx.x = n-half).
// ---------------------------------------------------------------------------
__global__ void __launch_bounds__(256,2) k_gemm2(const float* __restrict__ b2)
{
  extern __shared__ float sm[];
  const int g  = blockIdx.z;
  const int m0 = blockIdx.y * 128;
  const int hx = blockIdx.x;              // 0 or 1 (n-half)
  const int n0 = hx * 128;
  const float* Ap = g_h + ((size_t)g*NB + m0) * NHID;
  const float* Bp = g_w2t + (size_t)g*NPROJ*NHID + (size_t)n0*NHID;

  float c[4][4][4];
  mma_loop_128(Ap, Bp, NHID, NHID, NHID/32, sm, c);

  const int tid = threadIdx.x;
  const int lane = tid & 31, wid = tid >> 5;
  const int wm = (wid & 1)*64, wn = (wid >> 1)*32;
  const int gid = lane >> 2, tig = lane & 3;

  float* rp = sm;   // [128][4] partial sums (smem free after mainloop)

  const float* b2g = b2 + g*NPROJ + n0;
  #pragma unroll
  for (int mt=0;mt<4;mt++)
    #pragma unroll
    for (int half=0; half<2; half++){
      const int r = wm + mt*16 + half*8 + gid;
      float ps = 0.f;
      #pragma unroll
      for (int nt=0;nt<4;nt++){
        const int n = wn + nt*8 + tig*2;
        float x = c[mt][nt][half*2+0] + b2g[n];
        float y = c[mt][nt][half*2+1] + b2g[n+1];
        c[mt][nt][half*2+0] = x;
        c[mt][nt][half*2+1] = y;
        ps += x*x + y*y;
      }
      ps += __shfl_xor_sync(0xffffffffu, ps, 1);
      ps += __shfl_xor_sync(0xffffffffu, ps, 2);
      if (tig==0) rp[r*4 + (wid>>1)] = ps;
    }
  __syncthreads();
  if (tid < 128){
    const float ss = rp[tid*4+0]+rp[tid*4+1]+rp[tid*4+2]+rp[tid*4+3];
    g_ss[((size_t)g*NB + m0 + tid)*2 + hx] = ss;
  }
  float* Qp = g_qn + ((size_t)g*NB + m0) * NPROJ + n0;
  #pragma unroll
  for (int mt=0;mt<4;mt++)
    #pragma unroll
    for (int half=0; half<2; half++){
      const int r = wm + mt*16 + half*8 + gid;
      #pragma unroll
      for (int nt=0;nt<4;nt++){
        const int n = wn + nt*8 + tig*2;
        float2 v;
        v.x = c[mt][nt][half*2+0];
        v.y = c[mt][nt][half*2+1];
        *(float2*)(Qp + (size_t)r*NPROJ + n) = v;
      }
    }
}

// ---------------------------------------------------------------------------
// k_qnorm: g_qn row-normalize in place using g_ss partials. 8 rows/block.
// ---------------------------------------------------------------------------
__global__ void __launch_bounds__(256) k_qnorm()
{
  const int row = blockIdx.x * 8 + (threadIdx.x >> 5);
  const int lane = threadIdx.x & 31;
  const float ss = g_ss[row*2+0] + g_ss[row*2+1];
  const float inv = 1.f / fmaxf(sqrtf(ss), 1e-12f);
  float4* p = (float4*)(g_qn + (size_t)row * NPROJ);
  float4 a = p[lane];
  float4 b = p[lane+32];
  a.x*=inv; a.y*=inv; a.z*=inv; a.w*=inv;
  b.x*=inv; b.y*=inv; b.z*=inv; b.w*=inv;
  p[lane]    = a;
  p[lane+32] = b;
}

// ---------------------------------------------------------------------------
// GEMM3: out[b, g*CHUNK+v] = (qn . Wv[g,v]) * coef[g,v] + bv[g,v]
// (A=g_qn [g][4096][256], B=Wv [g][4096][256] already n-major)
// ---------------------------------------------------------------------------
__global__ void __launch_bounds__(256,2) k_gemm3(
    const float* __restrict__ Wv, const float* __restrict__ bv, float* __restrict__ out)
{
  extern __shared__ float sm[];
  const int g  = blockIdx.z;
  const int m0 = blockIdx.y * 128;
  const int n0 = blockIdx.x * 128;
  const float* Ap = g_qn + ((size_t)g*NB + m0) * NPROJ;
  const float* Bp = Wv + ((size_t)g*NCHUNK + n0) * NPROJ;

  float c[4][4][4];
  mma_loop_128(Ap, Bp, NPROJ, NPROJ, NPROJ/32, sm, c);

  const int lane = threadIdx.x & 31, wid = threadIdx.x >> 5;
  const int wm = (wid & 1)*64, wn = (wid >> 1)*32;
  const int gid = lane >> 2, tig = lane & 3;

  const float* cf  = g_coef + g*NCHUNK + n0;
  const float* bvg = bv     + g*NCHUNK + n0;
  float* O = out + (size_t)m0 * OUTLD + (size_t)g*NCHUNK + n0;
  #pragma unroll
  for (int mt=0;mt<4;mt++)
    #pragma unroll
    for (int half=0; half<2; half++){
      const int r = wm + mt*16 + half*8 + gid;
      #pragma unroll
      for (int nt=0;nt<4;nt++){
        const int n = wn + nt*8 + tig*2;
        float2 v;
        v.x = c[mt][nt][half*2+0]*cf[n]   + bvg[n];
        v.y = c[mt][nt][half*2+1]*cf[n+1] + bvg[n+1];
        *(float2*)(O + (size_t)r*OUTLD + n) = v;
      }
    }
}

// ---------------------------------------------------------------------------
extern "C" void kernel_launch(void* const* d_in, const int* in_sizes, int n_in,
                              void* d_out, int out_size)
{
  (void)in_sizes; (void)n_in; (void)out_size;
  const float* z   = (const float*)d_in[0];
  const float* W1  = (const float*)d_in[1];
  const float* b1  = (const float*)d_in[2];
  const float* lng = (const float*)d_in[3];
  const float* lnb = (const float*)d_in[4];
  const float* W2  = (const float*)d_in[5];
  const float* b2  = (const float*)d_in[6];
  const float* Wv  = (const float*)d_in[7];
  const float* bv  = (const float*)d_in[8];
  const float* ls  = (const float*)d_in[9];
  float* out = (float*)d_out;

  cudaFuncSetAttribute(k_gemm1, cudaFuncAttributeMaxDynamicSharedMemorySize, SMEM_A);
  cudaFuncSetAttribute(k_gemm2, cudaFuncAttributeMaxDynamicSharedMemorySize, SMEM_A);
  cudaFuncSetAttribute(k_gemm3, cudaFuncAttributeMaxDynamicSharedMemorySize, SMEM_A);

  float* w1t; cudaGetSymbolAddress((void**)&w1t, g_w1t);
  float* w2t; cudaGetSymbolAddress((void**)&w2t, g_w2t);

  // Pre-transpose weights to n-major (k-contiguous) layouts
  k_tr<<<dim3(NHID/32, NIN/32,  NG), dim3(32,8)>>>(W1, w1t, NIN,  NHID);
  k_tr<<<dim3(NPROJ/32, NHID/32, NG), dim3(32,8)>>>(W2, w2t, NHID, NPROJ);
  k_coef  <<<NG*NCHUNK/8, 256>>>(Wv, ls);

  k_gemm1 <<<dim3(NHID/128, NB/128, NG), 256, SMEM_A>>>(z, b1);
  k_lngelu<<<NG*NB, 256>>>(lng, lnb);
  k_gemm2 <<<dim3(2, NB/128, NG), 256, SMEM_A>>>(b2);
  k_qnorm <<<NG*NB/8, 256>>>();
  k_gemm3 <<<dim3(NCHUNK/128, NB/128, NG), 256, SMEM_A>>>(Wv, bv, out);
}

// round 17
// speedup vs baseline: 1.1900x; 1.0703x over previous
#include <cuda_runtime.h>
#include <cuda_bf16.h>
#include <math.h>

#define NB     4096
#define NG     16
#define NIN    1024
#define NHID   2048
#define NPROJ  256
#define NCHUNK 4096
#define OUTLD  (NG*NCHUNK)   /* 65536 */

// Scratch (device globals — no allocation allowed)
__device__ float g_h[(size_t)NG*NB*NHID];        // 512 MB
__device__ float g_qn[(size_t)NG*NB*NPROJ];      // 16 MB
__device__ float g_ss[(size_t)NG*NB*2];          // partial sumsq per row-half
__device__ float g_coef[NG*NCHUNK];
__device__ float g_w1t[(size_t)NG*NHID*NIN];     // 128 MB  W1^T [g][n][k]
__device__ float g_w2t[(size_t)NG*NPROJ*NHID];   // 8 MB    W2^T [g][p][h]

__device__ __forceinline__ unsigned s2u(const void* p){
  return (unsigned)__cvta_generic_to_shared(p);
}
__device__ __forceinline__ void cpa16(void* s, const void* g){
  asm volatile("cp.async.cg.shared.global [%0], [%1], 16;\n"
    :: "r"(s2u(s)), "l"(g));
}
__device__ __forceinline__ void ldsm4(unsigned &r0, unsigned &r1, unsigned &r2, unsigned &r3, unsigned addr){
  asm volatile("ldmatrix.sync.aligned.m8n8.x4.shared.b16 {%0,%1,%2,%3}, [%4];\n"
    : "=r"(r0), "=r"(r1), "=r"(r2), "=r"(r3) : "r"(addr) : "memory");
}
__device__ __forceinline__ void mma8(float* c, const unsigned* a, const unsigned* b){
  asm volatile(
    "mma.sync.aligned.m16n8k8.row.col.f32.tf32.tf32.f32 "
    "{%0,%1,%2,%3}, {%4,%5,%6,%7}, {%8,%9}, {%0,%1,%2,%3};\n"
    : "+f"(c[0]), "+f"(c[1]), "+f"(c[2]), "+f"(c[3])
    : "r"(a[0]), "r"(a[1]), "r"(a[2]), "r"(a[3]), "r"(b[0]), "r"(b[1]));
}

// mbarrier helpers
#define MBAR_INIT(a, c) \
  asm volatile("mbarrier.init.shared.b64 [%0], %1;" :: "r"((unsigned)(a)), "r"((unsigned)(c)) : "memory")
#define MBAR_ARRIVE(a) \
  asm volatile("mbarrier.arrive.shared.b64 _, [%0];" :: "r"((unsigned)(a)) : "memory")
// .noinc: deferred arrive counts against the init count (default variant
// would increment expected-count first and deadlock a pure-async barrier).
#define CPA_MBAR_ARRIVE(a) \
  asm volatile("cp.async.mbarrier.arrive.noinc.shared.b64 [%0];" :: "r"((unsigned)(a)) : "memory")
#define MBAR_WAIT(mbar_a, par) do { \
  unsigned _m = (unsigned)(mbar_a); unsigned _p = (unsigned)(par); unsigned _d; \
  asm volatile("{\n\t.reg .pred p;\n\t" \
    "mbarrier.try_wait.parity.acquire.cta.shared::cta.b64 p, [%1], %2;\n\t" \
    "selp.b32 %0, 1, 0, p;\n\t}" : "=r"(_d) : "r"(_m), "r"(_p) : "memory"); \
  if (!_d) { \
    asm volatile("{\n\t.reg .pred P1;\n\t" \
      "WL_%=:\n\t" \
      "mbarrier.try_wait.parity.acquire.cta.shared::cta.b64 P1, [%0], %1, 0x989680;\n\t" \
      "@P1 bra.uni WD_%=;\n\t" \
      "bra.uni WL_%=;\n\t" \
      "WD_%=:\n\t}" :: "r"(_m), "r"(_p) : "memory"); \
  } \
} while(0)

// ===========================================================================
// Variant A (all GEMMs): block 128x128, BK=32, 3-stage ring, 256 threads,
// 2 CTAs/SM. Warp grid 2(m) x 4(n); warp tile 64x32 (mt=4 x nt=4).
// mbarrier full/empty pipeline; producer issued mid-compute; empty released
// at last ldsm (lane0/warp, count 8).
// ===========================================================================
#define A_STRIDE 36                /* 32+4 pad; 36*4=144 ≡ 16 (mod 128) */
#define A_TSZ (128*A_STRIDE)       /* one 128-row tile, floats */
#define MBAR_OFF (6*A_TSZ*4)       /* byte offset of barriers in dynamic smem */
#define SMEM_A (MBAR_OFF + 64)     /* 110,656 B */

__device__ __forceinline__ void mma_loop_128(
  const float* __restrict__ Ap, const float* __restrict__ Bp,
  int lda, int ldb, int KT, float* sm, float (&c)[4][4][4])
{
  const int tid  = threadIdx.x;
  const int lane = tid & 31, wid = tid >> 5;
  const int wm   = (wid & 1) * 64;
  const int wn   = (wid >> 1) * 32;
  const int srow = tid >> 3, scol = (tid & 7) << 2;

  const unsigned mb   = s2u(sm) + MBAR_OFF;      // full[0..2] at +0,+8,+16
  const unsigned mbE  = mb + 24;                 // empty[0..2] at +24,+32,+40

  if (tid == 0){
    #pragma unroll
    for (int i=0;i<3;i++){ MBAR_INIT(mb + i*8, 256); MBAR_INIT(mbE + i*8, 8); }
  }
  __syncthreads();

  #pragma unroll
  for (int i=0;i<4;i++)
    #pragma unroll
    for (int j=0;j<4;j++)
      #pragma unroll
      for (int k=0;k<4;k++) c[i][j][k]=0.f;

  auto issue = [&](int s, int k0){
    float* as = sm + s*2*A_TSZ;
    float* bs = as + A_TSZ;
    #pragma unroll
    for (int i=0;i<4;i++)
      cpa16(&as[(srow+32*i)*A_STRIDE + scol], Ap + (size_t)(srow+32*i)*lda + k0 + scol);
    #pragma unroll
    for (int i=0;i<4;i++)
      cpa16(&bs[(srow+32*i)*A_STRIDE + scol], Bp + (size_t)(srow+32*i)*ldb + k0 + scol);
    CPA_MBAR_ARRIVE(mb + s*8);
  };
  issue(0, 0);
  issue(1, 32);

  const int a_r  = lane & 15;
  const int a_c4 = (lane >> 4) * 4;
  const int b_r  = (lane & 7) + ((lane >> 4) & 1) * 8;
  const int b_c4 = ((lane >> 3) & 1) * 4;

  for (int kt = 0; kt < KT; kt++){
    const int s  = kt % 3;
    const int ph = (kt / 3) & 1;

    // consumer: wait data for stage kt (per-thread, no CTA alignment)
    MBAR_WAIT(mb + s*8, ph);

    const unsigned as0 = s2u(sm + s*2*A_TSZ);
    const unsigned bs0 = as0 + (unsigned)(A_TSZ*4);

    unsigned a[4][4], b[2][4];
    // ks = 0: load + compute
    #pragma unroll
    for (int mt=0;mt<4;mt++){
      unsigned ad = as0 + (unsigned)(((wm + mt*16 + a_r)*A_STRIDE + a_c4)*4);
      ldsm4(a[mt][0],a[mt][1],a[mt][2],a[mt][3], ad);
    }
    #pragma unroll
    for (int np=0;np<2;np++){
      unsigned bd = bs0 + (unsigned)(((wn + np*16 + b_r)*A_STRIDE + b_c4)*4);
      ldsm4(b[np][0],b[np][1],b[np][2],b[np][3], bd);
    }
    #pragma unroll
    for (int mt=0;mt<4;mt++)
      #pragma unroll
      for (int np=0;np<2;np++){
        mma8(c[mt][np*2+0], a[mt], &b[np][0]);
        mma8(c[mt][np*2+1], a[mt], &b[np][2]);
      }

    // producer for stage kt+2, issued mid-compute (lagging warps have had
    // ~64 MMAs of slack to release empty[kt+2])
    const int kl = kt + 2;
    if (kl < KT){
      const int sl = kl % 3;
      if (kl >= 3) MBAR_WAIT(mbE + sl*8, ((kl - 3) / 3) & 1);
      issue(sl, kl*32);
    }

    // ks = 1..3
    #pragma unroll
    for (int ks=1; ks<4; ks++){
      const int kb = ks*8;
      #pragma unroll
      for (int mt=0;mt<4;mt++){
        unsigned ad = as0 + (unsigned)(((wm + mt*16 + a_r)*A_STRIDE + kb + a_c4)*4);
        ldsm4(a[mt][0],a[mt][1],a[mt][2],a[mt][3], ad);
      }
      #pragma unroll
      for (int np=0;np<2;np++){
        unsigned bd = bs0 + (unsigned)(((wn + np*16 + b_r)*A_STRIDE + kb + b_c4)*4);
        ldsm4(b[np][0],b[np][1],b[np][2],b[np][3], bd);
      }
      if (ks == 3 && lane == 0) MBAR_ARRIVE(mbE + s*8);  // smem reads done
      #pragma unroll
      for (int mt=0;mt<4;mt++)
        #pragma unroll
        for (int np=0;np<2;np++){
          mma8(c[mt][np*2+0], a[mt], &b[np][0]);
          mma8(c[mt][np*2+1], a[mt], &b[np][2]);
        }
    }
  }
  __syncthreads();
}

// ---------------------------------------------------------------------------
// Transpose: src [g][R][C] -> dst [g][C][R]
// ---------------------------------------------------------------------------
__global__ void k_tr(const float* __restrict__ src, float* __restrict__ dst, int R, int C)
{
  __shared__ float t[32][33];
  const int g = blockIdx.z;
  src += (size_t)g*R*C;
  dst += (size_t)g*R*C;
  const int c0 = blockIdx.x*32, r0 = blockIdx.y*32;
  const int x = threadIdx.x, y = threadIdx.y;
  #pragma unroll
  for (int j=0;j<32;j+=8)
    t[y+j][x] = src[(size_t)(r0+y+j)*C + c0+x];
  __syncthreads();
  #pragma unroll
  for (int j=0;j<32;j+=8)
    dst[(size_t)(c0+y+j)*R + r0+x] = t[x][y+j];
}

// ---------------------------------------------------------------------------
// GEMM1: h = z @ W1 + b1   (A=z [4096][1024], B=w1t [g][2048][1024])
// ---------------------------------------------------------------------------
__global__ void __launch_bounds__(256,2) k_gemm1(
    const float* __restrict__ z, const float* __restrict__ b1)
{
  extern __shared__ float sm[];
  const int g  = blockIdx.z;
  const int m0 = blockIdx.y * 128;
  const int n0 = blockIdx.x * 128;
  const float* Ap = z + (size_t)m0 * NIN;
  const float* Bp = g_w1t + (size_t)g*NHID*NIN + (size_t)n0*NIN;

  float c[4][4][4];
  mma_loop_128(Ap, Bp, NIN, NIN, NIN/32, sm, c);

  const int lane = threadIdx.x & 31, wid = threadIdx.x >> 5;
  const int wm = (wid & 1)*64, wn = (wid >> 1)*32;
  const int gid = lane >> 2, tig = lane & 3;
  const float* b1g = b1 + g*NHID + n0;
  float* H = g_h + ((size_t)g*NB + m0) * NHID + n0;
  #pragma unroll
  for (int mt=0;mt<4;mt++)
    #pragma unroll
    for (int half=0; half<2; half++){
      const int r = wm + mt*16 + half*8 + gid;
      #pragma unroll
      for (int nt=0;nt<4;nt++){
        const int n = wn + nt*8 + tig*2;
        float2 v;
        v.x = c[mt][nt][half*2+0] + b1g[n];
        v.y = c[mt][nt][half*2+1] + b1g[n+1];
        *(float2*)(H + (size_t)r*NHID + n) = v;
      }
    }
}

// ---------------------------------------------------------------------------
// K2: per-row LayerNorm + exact-erf GELU, in place on g_h. 1 block / row.
// ---------------------------------------------------------------------------
__global__ void __launch_bounds__(256) k_lngelu(
    const float* __restrict__ ln_g, const float* __restrict__ ln_b)
{
  const int row = blockIdx.x;           // 0 .. G*B-1
  const int g   = row >> 12;
  float* base = g_h + (size_t)row * NHID;
  const int tid = threadIdx.x;
  const int lane = tid & 31, wid = tid >> 5;

  float4 v0 = ((const float4*)base)[tid];
  float4 v1 = ((const float4*)base)[tid + 256];
  float s = v0.x+v0.y+v0.z+v0.w + v1.x+v1.y+v1.z+v1.w;
  float q = v0.x*v0.x+v0.y*v0.y+v0.z*v0.z+v0.w*v0.w
          + v1.x*v1.x+v1.y*v1.y+v1.z*v1.z+v1.w*v1.w;
  #pragma unroll
  for (int o=16;o;o>>=1){
    s += __shfl_xor_sync(0xffffffffu, s, o);
    q += __shfl_xor_sync(0xffffffffu, q, o);
  }
  __shared__ float rs[8], rq[8];
  if (lane==0){ rs[wid]=s; rq[wid]=q; }
  __syncthreads();
  if (tid==0){
    float S=0.f, Q=0.f;
    #pragma unroll
    for (int i=0;i<8;i++){ S+=rs[i]; Q+=rq[i]; }
    rs[0]=S; rq[0]=Q;
  }
  __syncthreads();
  const float S = rs[0], Q = rq[0];
  const float mu   = S * (1.f/NHID);
  const float var  = Q * (1.f/NHID) - mu*mu;
  const float rsig = rsqrtf(var + 1e-5f);

  const float* lg = ln_g + g*NHID;
  const float* lb = ln_b + g*NHID;
  const float isq2 = 0.70710678118654752440f;

  const int c0 = tid*4, c1 = (tid+256)*4;
  float xs[8] = {v0.x,v0.y,v0.z,v0.w, v1.x,v1.y,v1.z,v1.w};
  int   cs[8] = {c0,c0+1,c0+2,c0+3, c1,c1+1,c1+2,c1+3};
  float ys[8];
  #pragma unroll
  for (int i=0;i<8;i++){
    float y = (xs[i]-mu)*rsig*lg[cs[i]] + lb[cs[i]];
    ys[i] = 0.5f*y*(1.f + erff(y*isq2));
  }
  ((float4*)base)[tid]       = make_float4(ys[0],ys[1],ys[2],ys[3]);
  ((float4*)base)[tid + 256] = make_float4(ys[4],ys[5],ys[6],ys[7]);
}

// ---------------------------------------------------------------------------
// K3: coef[g,v] = min(exp(logit_scale[g]),100) / max(||Wv[g,v,:]||, 1e-12)
// ---------------------------------------------------------------------------
__global__ void __launch_bounds__(256) k_coef(
    const float* __restrict__ Wv, const float* __restrict__ logit_scale)
{
  const int tid = threadIdx.x;
  const int wid = tid >> 5, lane = tid & 31;
  const int row = blockIdx.x * 8 + wid;     // 0 .. G*CHUNK-1
  const float* p = Wv + (size_t)row * NPROJ;
  float4 a = ((const float4*)p)[lane];
  float4 b = ((const float4*)p)[lane + 32];
  float s = a.x*a.x+a.y*a.y+a.z*a.z+a.w*a.w
          + b.x*b.x+b.y*b.y+b.z*b.z+b.w*b.w;
  #pragma unroll
  for (int o=16;o;o>>=1) s += __shfl_xor_sync(0xffffffffu, s, o);
  if (lane==0){
    const int g = row >> 12;
    const float sc = fminf(expf(logit_scale[g]), 100.f);
    g_coef[row] = sc / fmaxf(sqrtf(s), 1e-12f);
  }
}

// ---------------------------------------------------------------------------
// GEMM2: q = gelu_h @ W2 + b2 -> g_qn (unnormalized) + per-half sumsq g_ss.
// 128x128 tiles, 2 CTAs per m-row (blockIdx.x = n-half).
// ---------------------------------------------------------------------------
__global__ void __launch_bounds__(256,2) k_gemm2(const float* __restrict__ b2)
{
  extern __shared__ float sm[];
  const int g  = blockIdx.z;
  const int m0 = blockIdx.y * 128;
  const int hx = blockIdx.x;              // 0 or 1 (n-half)
  const int n0 = hx * 128;
  const float* Ap = g_h + ((size_t)g*NB + m0) * NHID;
  const float* Bp = g_w2t + (size_t)g*NPROJ*NHID + (size_t)n0*NHID;

  float c[4][4][4];
  mma_loop_128(Ap, Bp, NHID, NHID, NHID/32, sm, c);

  const int tid = threadIdx.x;
  const int lane = tid & 31, wid = tid >> 5;
  const int wm = (wid & 1)*64, wn = (wid >> 1)*32;
  const int gid = lane >> 2, tig = lane & 3;

  float* rp = sm;   // [128][4] partial sums (smem free after mainloop)

  const float* b2g = b2 + g*NPROJ + n0;
  #pragma unroll
  for (int mt=0;mt<4;mt++)
    #pragma unroll
    for (int half=0; half<2; half++){
      const int r = wm + mt*16 + half*8 + gid;
      float ps = 0.f;
      #pragma unroll
      for (int nt=0;nt<4;nt++){
        const int n = wn + nt*8 + tig*2;
        float x = c[mt][nt][half*2+0] + b2g[n];
        float y = c[mt][nt][half*2+1] + b2g[n+1];
        c[mt][nt][half*2+0] = x;
        c[mt][nt][half*2+1] = y;
        ps += x*x + y*y;
      }
      ps += __shfl_xor_sync(0xffffffffu, ps, 1);
      ps += __shfl_xor_sync(0xffffffffu, ps, 2);
      if (tig==0) rp[r*4 + (wid>>1)] = ps;
    }
  __syncthreads();
  if (tid < 128){
    const float ss = rp[tid*4+0]+rp[tid*4+1]+rp[tid*4+2]+rp[tid*4+3];
    g_ss[((size_t)g*NB + m0 + tid)*2 + hx] = ss;
  }
  float* Qp = g_qn + ((size_t)g*NB + m0) * NPROJ + n0;
  #pragma unroll
  for (int mt=0;mt<4;mt++)
    #pragma unroll
    for (int half=0; half<2; half++){
      const int r = wm + mt*16 + half*8 + gid;
      #pragma unroll
      for (int nt=0;nt<4;nt++){
        const int n = wn + nt*8 + tig*2;
        float2 v;
        v.x = c[mt][nt][half*2+0];
        v.y = c[mt][nt][half*2+1];
        *(float2*)(Qp + (size_t)r*NPROJ + n) = v;
      }
    }
}

// ---------------------------------------------------------------------------
// k_qnorm: g_qn row-normalize in place using g_ss partials. 8 rows/block.
// ---------------------------------------------------------------------------
__global__ void __launch_bounds__(256) k_qnorm()
{
  const int row = blockIdx.x * 8 + (threadIdx.x >> 5);
  const int lane = threadIdx.x & 31;
  const float ss = g_ss[row*2+0] + g_ss[row*2+1];
  const float inv = 1.f / fmaxf(sqrtf(ss), 1e-12f);
  float4* p = (float4*)(g_qn + (size_t)row * NPROJ);
  float4 a = p[lane];
  float4 b = p[lane+32];
  a.x*=inv; a.y*=inv; a.z*=inv; a.w*=inv;
  b.x*=inv; b.y*=inv; b.z*=inv; b.w*=inv;
  p[lane]    = a;
  p[lane+32] = b;
}

// ---------------------------------------------------------------------------
// GEMM3: out[b, g*CHUNK+v] = (qn . Wv[g,v]) * coef[g,v] + bv[g,v]
// (A=g_qn [g][4096][256], B=Wv [g][4096][256] already n-major)
// ---------------------------------------------------------------------------
__global__ void __launch_bounds__(256,2) k_gemm3(
    const float* __restrict__ Wv, const float* __restrict__ bv, float* __restrict__ out)
{
  extern __shared__ float sm[];
  const int g  = blockIdx.z;
  const int m0 = blockIdx.y * 128;
  const int n0 = blockIdx.x * 128;
  const float* Ap = g_qn + ((size_t)g*NB + m0) * NPROJ;
  const float* Bp = Wv + ((size_t)g*NCHUNK + n0) * NPROJ;

  float c[4][4][4];
  mma_loop_128(Ap, Bp, NPROJ, NPROJ, NPROJ/32, sm, c);

  const int lane = threadIdx.x & 31, wid = threadIdx.x >> 5;
  const int wm = (wid & 1)*64, wn = (wid >> 1)*32;
  const int gid = lane >> 2, tig = lane & 3;

  const float* cf  = g_coef + g*NCHUNK + n0;
  const float* bvg = bv     + g*NCHUNK + n0;
  float* O = out + (size_t)m0 * OUTLD + (size_t)g*NCHUNK + n0;
  #pragma unroll
  for (int mt=0;mt<4;mt++)
    #pragma unroll
    for (int half=0; half<2; half++){
      const int r = wm + mt*16 + half*8 + gid;
      #pragma unroll
      for (int nt=0;nt<4;nt++){
        const int n = wn + nt*8 + tig*2;
        float2 v;
        v.x = c[mt][nt][half*2+0]*cf[n]   + bvg[n];
        v.y = c[mt][nt][half*2+1]*cf[n+1] + bvg[n+1];
        *(float2*)(O + (size_t)r*OUTLD + n) = v;
      }
    }
}

// ---------------------------------------------------------------------------
extern "C" void kernel_launch(void* const* d_in, const int* in_sizes, int n_in,
                              void* d_out, int out_size)
{
  (void)in_sizes; (void)n_in; (void)out_size;
  const float* z   = (const float*)d_in[0];
  const float* W1  = (const float*)d_in[1];
  const float* b1  = (const float*)d_in[2];
  const float* lng = (const float*)d_in[3];
  const float* lnb = (const float*)d_in[4];
  const float* W2  = (const float*)d_in[5];
  const float* b2  = (const float*)d_in[6];
  const float* Wv  = (const float*)d_in[7];
  const float* bv  = (const float*)d_in[8];
  const float* ls  = (const float*)d_in[9];
  float* out = (float*)d_out;

  cudaFuncSetAttribute(k_gemm1, cudaFuncAttributeMaxDynamicSharedMemorySize, SMEM_A);
  cudaFuncSetAttribute(k_gemm2, cudaFuncAttributeMaxDynamicSharedMemorySize, SMEM_A);
  cudaFuncSetAttribute(k_gemm3, cudaFuncAttributeMaxDynamicSharedMemorySize, SMEM_A);

  float* w1t; cudaGetSymbolAddress((void**)&w1t, g_w1t);
  float* w2t; cudaGetSymbolAddress((void**)&w2t, g_w2t);

  // Pre-transpose weights to n-major (k-contiguous) layouts
  k_tr<<<dim3(NHID/32, NIN/32,  NG), dim3(32,8)>>>(W1, w1t, NIN,  NHID);
  k_tr<<<dim3(NPROJ/32, NHID/32, NG), dim3(32,8)>>>(W2, w2t, NHID, NPROJ);
  k_coef  <<<NG*NCHUNK/8, 256>>>(Wv, ls);

  k_gemm1 <<<dim3(NHID/128, NB/128, NG), 256, SMEM_A>>>(z, b1);
  k_lngelu<<<NG*NB, 256>>>(lng, lnb);
  k_gemm2 <<<dim3(2, NB/128, NG), 256, SMEM_A>>>(b2);
  k_qnorm <<<NG*NB/8, 256>>>();
  k_gemm3 <<<dim3(NCHUNK/128, NB/128, NG), 256, SMEM_A>>>(Wv, bv, out);
}